// round 12
// baseline (speedup 1.0000x reference)
#include <cuda_runtime.h>
#include <cuda_bf16.h>
#include <cstdint>

// ---------------------------------------------------------------------------
// HyperbolicGraphPooling: out[g] = sum_{n: batch[n]==g} sigmoid(f[n]·W+b) * f[n]
// N=500000, C=256, 2048 graphs, batch int32 sorted ascending.
// R12: FUSED single kernel. Zero pass + software grid barrier (monotonic
// epoch counter, no reset needed across graph replays) folded into the pool
// kernel; warps wait for the release epoch LAZILY before their first flush,
// so the barrier is off the streaming critical path. Removes the ~3us of
// launch/drain serialization left in R11 (end-to-end 86.5 vs kernel 83.4).
// Target ~83.5-85 us.
// ---------------------------------------------------------------------------

#define CHANNELS 256
#define THREADS  256
#define WARPS    (THREADS / 32)
#define STAGES   4
#define GRID     740   // 148 SMs * 5 blocks -> exactly one co-resident wave

__device__ unsigned int g_bar_count;   // monotonic across replays; no reset

__device__ __forceinline__ void wait_release(bool& waited,
                                             const unsigned int* tgt_sh,
                                             int lane) {
    if (!waited) {
        if (lane == 0) {
            const unsigned int target = *tgt_sh;
            // Spin until all GRID blocks of this replay's epoch have arrived.
            while (true) {
                unsigned int v;
                asm volatile("ld.volatile.global.u32 %0, [%1];"
                             : "=r"(v) : "l"(&g_bar_count));
                if ((int)(v - target) >= 0) break;
                __nanosleep(64);
            }
        }
        __syncwarp(0xFFFFFFFFu);
        __threadfence();   // acquire: zero-stores visible before our atomics
        waited = true;
    }
}

__device__ __forceinline__ void flush_seg(float* __restrict__ out,
                                          int seg, int num_segs, int lane,
                                          const float4& a0, const float4& a1) {
    if (seg < 0 || seg >= num_segs) return;   // defensive
    float* p0 = out + (size_t)seg * CHANNELS + 4 * lane;
    float* p1 = p0 + 128;
    atomicAdd(p0 + 0, a0.x);
    atomicAdd(p0 + 1, a0.y);
    atomicAdd(p0 + 2, a0.z);
    atomicAdd(p0 + 3, a0.w);
    atomicAdd(p1 + 0, a1.x);
    atomicAdd(p1 + 1, a1.y);
    atomicAdd(p1 + 2, a1.z);
    atomicAdd(p1 + 3, a1.w);
}

__device__ __forceinline__ void cp_row(unsigned int s_dst,
                                       const float* __restrict__ feat,
                                       int row, int lane) {
    // Each lane copies its own 32B: channels [4*lane,4*lane+4) and +128.
    const char* g = reinterpret_cast<const char*>(feat + (size_t)row * CHANNELS)
                    + lane * 16;
    asm volatile("cp.async.cg.shared.global [%0], [%1], 16;\n"
                 "cp.async.cg.shared.global [%2], [%3], 16;"
                 :: "r"(s_dst + lane * 16), "l"(g),
                    "r"(s_dst + 512 + lane * 16), "l"(g + 512));
}

__global__ __launch_bounds__(THREADS, 5)
void hgp_fused_kernel(const float* __restrict__ feat,
                      const int* __restrict__ batch,
                      const float* __restrict__ W,
                      const float* __restrict__ b,
                      float* __restrict__ out,
                      int N, int num_segs) {
    __shared__ __align__(16) float ring[WARPS][STAGES][CHANNELS];
    __shared__ unsigned int s_target;

    const int lane        = threadIdx.x & 31;
    const int wid         = threadIdx.x >> 5;
    const int tid_global  = blockIdx.x * blockDim.x + threadIdx.x;
    const int warp_global = tid_global >> 5;
    const int total_warps = (gridDim.x * blockDim.x) >> 5;

    // ---- Phase 1: zero our slice of out (one float4 per thread) ----------
    {
        const int n4 = num_segs * (CHANNELS / 4);
        if (tid_global < n4)
            reinterpret_cast<float4*>(out)[tid_global] =
                make_float4(0.f, 0.f, 0.f, 0.f);
        __threadfence();        // our zero-stores globally visible
    }
    __syncthreads();            // whole block's zeroing + fences done

    // ---- Phase 2: one arrival per block; compute release epoch ------------
    if (threadIdx.x == 0) {
        const unsigned int t = atomicAdd(&g_bar_count, 1u);
        s_target = (t / GRID + 1u) * GRID;   // end of this replay's epoch
    }
    __syncthreads();            // s_target visible to all warps

    // ---- Phase 3: stream (identical to R11 pool kernel) -------------------
    const int per = (N + total_warps - 1) / total_warps;
    const int n0  = warp_global * per;
    const int n1  = (n0 + per < N) ? (n0 + per) : N;
    if (n0 >= n1) return;       // barrier arrival already done above

    const unsigned int s_base =
        (unsigned int)__cvta_generic_to_shared(&ring[wid][0][0]);

    const float4 w0 = *reinterpret_cast<const float4*>(W + 4 * lane);
    const float4 w1 = *reinterpret_cast<const float4*>(W + 128 + 4 * lane);
    const float bias = b[0];

    float4 a0 = make_float4(0.f, 0.f, 0.f, 0.f);
    float4 a1 = make_float4(0.f, 0.f, 0.f, 0.f);
    int cur = __ldg(batch + n0);
    bool waited = false;        // lazy grid-barrier wait before first flush

    // Prologue: issue rows n0 .. n0+STAGES-2, one commit group per row.
    #pragma unroll
    for (int p = 0; p < STAGES - 1; ++p) {
        const int pn = n0 + p;
        if (pn < n1)
            cp_row(s_base + ((pn & (STAGES - 1)) << 10), feat, pn, lane);
        asm volatile("cp.async.commit_group;" ::: "memory");
    }

    for (int n = n0; n < n1; ++n) {
        const int pn = n + STAGES - 1;
        if (pn < n1)
            cp_row(s_base + ((pn & (STAGES - 1)) << 10), feat, pn, lane);
        asm volatile("cp.async.commit_group;" ::: "memory");

        const int g = __ldg(batch + n);

        // Row n's group is the 4th most recent => wait_group 3 suffices.
        asm volatile("cp.async.wait_group 3;" ::: "memory");

        const float* srow = &ring[wid][n & (STAGES - 1)][0];
        const float4 f0 = *reinterpret_cast<const float4*>(srow + 4 * lane);
        const float4 f1 = *reinterpret_cast<const float4*>(srow + 128 + 4 * lane);

        if (g != cur) {
            wait_release(waited, &s_target, lane);
            flush_seg(out, cur, num_segs, lane, a0, a1);
            a0 = make_float4(0.f, 0.f, 0.f, 0.f);
            a1 = make_float4(0.f, 0.f, 0.f, 0.f);
            cur = g;
        }

        float s = f0.x * w0.x + f0.y * w0.y + f0.z * w0.z + f0.w * w0.w
                + f1.x * w1.x + f1.y * w1.y + f1.z * w1.z + f1.w * w1.w;
        #pragma unroll
        for (int o = 16; o > 0; o >>= 1)
            s += __shfl_xor_sync(0xFFFFFFFFu, s, o);

        const float wgt = __fdividef(1.0f, 1.0f + __expf(-(s + bias)));

        a0.x += f0.x * wgt; a0.y += f0.y * wgt;
        a0.z += f0.z * wgt; a0.w += f0.w * wgt;
        a1.x += f1.x * wgt; a1.y += f1.y * wgt;
        a1.z += f1.z * wgt; a1.w += f1.w * wgt;
    }

    wait_release(waited, &s_target, lane);
    flush_seg(out, cur, num_segs, lane, a0, a1);
}

extern "C" void kernel_launch(void* const* d_in, const int* in_sizes, int n_in,
                              void* d_out, int out_size) {
    const float* feat  = (const float*)d_in[0];  // [N, 256] f32
    const int*   batch = (const int*)d_in[1];    // [N] i32, sorted
    const float* W     = (const float*)d_in[2];  // [256, 1] f32
    const float* b     = (const float*)d_in[3];  // [1] f32
    float*       out   = (float*)d_out;          // [num_segs, 256] f32

    const int N        = in_sizes[1];
    const int num_segs = out_size / CHANNELS;    // 2048

    // Single fused kernel: zero + grid barrier + pool. One graph node.
    hgp_fused_kernel<<<GRID, THREADS>>>(feat, batch, W, b, out, N, num_segs);
}

// round 13
// speedup vs baseline: 1.0460x; 1.0460x over previous
#include <cuda_runtime.h>
#include <cuda_bf16.h>
#include <cstdint>

// ---------------------------------------------------------------------------
// HyperbolicGraphPooling: out[g] = sum_{n: batch[n]==g} sigmoid(f[n]·W+b) * f[n]
// N=500000, C=256, 2048 graphs, batch int32 sorted ascending.
// R13 = R11 (best: 86.5us end-to-end, kernel 83.4us @ 6.29TB/s ~= 98% of the
// demonstrated bandwidth plateau) + prologue reorder: cp.async groups issued
// BEFORE the scalar W/b/batch loads so row requests enter the memory system
// earlier. R12 (fused zero+barrier) regressed -> two-kernel PDL retained.
// ---------------------------------------------------------------------------

#define CHANNELS 256
#define THREADS  256
#define WARPS    (THREADS / 32)
#define STAGES   4

__global__ void hgp_zero_kernel(float4* __restrict__ out, int n4) {
    int i = blockIdx.x * blockDim.x + threadIdx.x;
    if (i < n4) out[i] = make_float4(0.f, 0.f, 0.f, 0.f);
    // Allow the dependent (pool) kernel to begin launching now.
    asm volatile("griddepcontrol.launch_dependents;" ::: "memory");
}

__device__ __forceinline__ void pdl_wait_once(bool& waited) {
    if (!waited) {
        // Block until the zero kernel's stores are globally visible.
        asm volatile("griddepcontrol.wait;" ::: "memory");
        waited = true;
    }
}

__device__ __forceinline__ void flush_seg(float* __restrict__ out,
                                          int seg, int num_segs, int lane,
                                          const float4& a0, const float4& a1) {
    if (seg < 0 || seg >= num_segs) return;   // defensive
    float* p0 = out + (size_t)seg * CHANNELS + 4 * lane;
    float* p1 = p0 + 128;
    atomicAdd(p0 + 0, a0.x);
    atomicAdd(p0 + 1, a0.y);
    atomicAdd(p0 + 2, a0.z);
    atomicAdd(p0 + 3, a0.w);
    atomicAdd(p1 + 0, a1.x);
    atomicAdd(p1 + 1, a1.y);
    atomicAdd(p1 + 2, a1.z);
    atomicAdd(p1 + 3, a1.w);
}

__device__ __forceinline__ void cp_row(unsigned int s_dst,
                                       const float* __restrict__ feat,
                                       int row, int lane) {
    // Each lane copies its own 32B: channels [4*lane,4*lane+4) and +128.
    const char* g = reinterpret_cast<const char*>(feat + (size_t)row * CHANNELS)
                    + lane * 16;
    asm volatile("cp.async.cg.shared.global [%0], [%1], 16;\n"
                 "cp.async.cg.shared.global [%2], [%3], 16;"
                 :: "r"(s_dst + lane * 16), "l"(g),
                    "r"(s_dst + 512 + lane * 16), "l"(g + 512));
}

__global__ __launch_bounds__(THREADS, 5)
void hgp_pool_kernel(const float* __restrict__ feat,
                     const int* __restrict__ batch,
                     const float* __restrict__ W,
                     const float* __restrict__ b,
                     float* __restrict__ out,
                     int N, int num_segs) {
    __shared__ __align__(16) float ring[WARPS][STAGES][CHANNELS];

    const int lane        = threadIdx.x & 31;
    const int wid         = threadIdx.x >> 5;
    const int warp_global = (blockIdx.x * blockDim.x + threadIdx.x) >> 5;
    const int total_warps = (gridDim.x * blockDim.x) >> 5;

    const int per = (N + total_warps - 1) / total_warps;
    const int n0  = warp_global * per;
    const int n1  = (n0 + per < N) ? (n0 + per) : N;
    if (n0 >= n1) return;

    const unsigned int s_base =
        (unsigned int)__cvta_generic_to_shared(&ring[wid][0][0]);

    // ---- Prologue FIRST: get row requests into the memory system before
    // any scalar loads (W / bias / batch) occupy the LSU.
    #pragma unroll
    for (int p = 0; p < STAGES - 1; ++p) {
        const int pn = n0 + p;
        if (pn < n1)
            cp_row(s_base + ((pn & (STAGES - 1)) << 10), feat, pn, lane);
        asm volatile("cp.async.commit_group;" ::: "memory");
    }

    const float4 w0 = *reinterpret_cast<const float4*>(W + 4 * lane);
    const float4 w1 = *reinterpret_cast<const float4*>(W + 128 + 4 * lane);
    const float bias = b[0];

    float4 a0 = make_float4(0.f, 0.f, 0.f, 0.f);
    float4 a1 = make_float4(0.f, 0.f, 0.f, 0.f);
    int cur = __ldg(batch + n0);
    bool waited = false;   // PDL: wait for zero kernel before first flush

    for (int n = n0; n < n1; ++n) {
        // Issue row n+3 into its slot, commit (possibly empty near the end).
        const int pn = n + STAGES - 1;
        if (pn < n1)
            cp_row(s_base + ((pn & (STAGES - 1)) << 10), feat, pn, lane);
        asm volatile("cp.async.commit_group;" ::: "memory");

        const int g = __ldg(batch + n);

        // Row n's group is the 4th most recent => wait_group 3 suffices.
        asm volatile("cp.async.wait_group 3;" ::: "memory");

        // Each lane reads back exactly the 32B it wrote (no cross-lane smem,
        // so per-thread cp.async visibility suffices; no __syncwarp needed).
        const float* srow = &ring[wid][n & (STAGES - 1)][0];
        const float4 f0 = *reinterpret_cast<const float4*>(srow + 4 * lane);
        const float4 f1 = *reinterpret_cast<const float4*>(srow + 128 + 4 * lane);

        if (g != cur) {
            pdl_wait_once(waited);
            flush_seg(out, cur, num_segs, lane, a0, a1);
            a0 = make_float4(0.f, 0.f, 0.f, 0.f);
            a1 = make_float4(0.f, 0.f, 0.f, 0.f);
            cur = g;
        }

        float s = f0.x * w0.x + f0.y * w0.y + f0.z * w0.z + f0.w * w0.w
                + f1.x * w1.x + f1.y * w1.y + f1.z * w1.z + f1.w * w1.w;
        #pragma unroll
        for (int o = 16; o > 0; o >>= 1)
            s += __shfl_xor_sync(0xFFFFFFFFu, s, o);

        const float wgt = __fdividef(1.0f, 1.0f + __expf(-(s + bias)));

        a0.x += f0.x * wgt; a0.y += f0.y * wgt;
        a0.z += f0.z * wgt; a0.w += f0.w * wgt;
        a1.x += f1.x * wgt; a1.y += f1.y * wgt;
        a1.z += f1.z * wgt; a1.w += f1.w * wgt;
    }

    pdl_wait_once(waited);
    flush_seg(out, cur, num_segs, lane, a0, a1);
}

extern "C" void kernel_launch(void* const* d_in, const int* in_sizes, int n_in,
                              void* d_out, int out_size) {
    const float* feat  = (const float*)d_in[0];  // [N, 256] f32
    const int*   batch = (const int*)d_in[1];    // [N] i32, sorted
    const float* W     = (const float*)d_in[2];  // [256, 1] f32
    const float* b     = (const float*)d_in[3];  // [1] f32
    float*       out   = (float*)d_out;          // [num_segs, 256] f32

    const int N        = in_sizes[1];
    const int num_segs = out_size / CHANNELS;    // 2048

    // Zero output (harness poisons it before each timed replay).
    const int n4 = out_size / 4;
    hgp_zero_kernel<<<(n4 + THREADS - 1) / THREADS, THREADS>>>(
        (float4*)out, n4);

    // Pool kernel launched with PDL so it overlaps the zero kernel's tail;
    // it synchronizes via griddepcontrol.wait before its first flush.
    {
        cudaLaunchConfig_t cfg = {};
        cfg.gridDim  = dim3(740, 1, 1);   // 148 SMs * 5 blocks, one wave
        cfg.blockDim = dim3(THREADS, 1, 1);
        cfg.dynamicSmemBytes = 0;
        cfg.stream = 0;
        cudaLaunchAttribute attrs[1];
        attrs[0].id = cudaLaunchAttributeProgrammaticStreamSerialization;
        attrs[0].val.programmaticStreamSerializationAllowed = 1;
        cfg.attrs = attrs;
        cfg.numAttrs = 1;
        cudaLaunchKernelEx(&cfg, hgp_pool_kernel,
                           feat, batch, W, b, out, N, num_segs);
    }
}